// round 16
// baseline (speedup 1.0000x reference)
#include <cuda_runtime.h>
#include <cuda_fp16.h>
#include <cstdint>
#include <math.h>

// ---------------------------------------------------------------------------
// Problem constants
// ---------------------------------------------------------------------------
#define TSEQ   2048
#define HID    2048
#define QDIM   4096   // 32 rope-heads * 128
#define KVDIM  1024   // 8 kv heads * 128
#define QKVDIM 6144   // QDIM + 2*KVDIM (merged projection width)
#define HD     128
#define NH16   16
#define NKV    8
#define HQ     32

#define ATT_SCALE 0.08838834764831845f   // 1/sqrt(128)

// ---------------------------------------------------------------------------
// Static device scratch (no allocations allowed)
// ---------------------------------------------------------------------------
__device__ __half   g_x16 [TSEQ * HID];
__device__ __half   g_wqkv[QKVDIM * HID];     // merged [Wq;Wk;Wv]^T, K-major
__device__ float    g_qkv [TSEQ * QKVDIM];    // merged q|k|v fp32
__device__ __half   g_qr  [TSEQ * QDIM];
__device__ __half   g_kr  [TSEQ * KVDIM];
__device__ __half   g_att [TSEQ * QDIM];
__device__ __half   g_wot [HID * QDIM];
__device__ __half   g_vt  [KVDIM * TSEQ];
__device__ float    g_s   [134217728];        // 32 * 2048 * 2048 fp32 S
__device__ __half   g_p   [134217728];        // 32 * 2048 * 2048 fp16 P

// ---------------------------------------------------------------------------
// Helpers
// ---------------------------------------------------------------------------
__device__ __forceinline__ uint32_t pk_h2(float a, float b) {
    __half2 h = __floats2half2_rn(a, b);
    return *reinterpret_cast<uint32_t*>(&h);
}

__device__ __forceinline__ uint32_t smem_u32(const void* p) {
    uint32_t a;
    asm("{ .reg .u64 t; cvta.to.shared.u64 t, %1; cvt.u32.u64 %0, t; }"
        : "=r"(a) : "l"(p));
    return a;
}

__device__ __forceinline__ void mma_f16(
    float& d0, float& d1, float& d2, float& d3,
    uint32_t a0, uint32_t a1, uint32_t a2, uint32_t a3,
    uint32_t b0, uint32_t b1)
{
    asm volatile(
        "mma.sync.aligned.m16n8k16.row.col.f32.f16.f16.f32 "
        "{%0,%1,%2,%3}, {%4,%5,%6,%7}, {%8,%9}, {%0,%1,%2,%3};"
        : "+f"(d0), "+f"(d1), "+f"(d2), "+f"(d3)
        : "r"(a0), "r"(a1), "r"(a2), "r"(a3), "r"(b0), "r"(b1));
}

__device__ __forceinline__ void ldsm4(
    uint32_t& r0, uint32_t& r1, uint32_t& r2, uint32_t& r3, uint32_t addr)
{
    asm volatile(
        "ldmatrix.sync.aligned.m8n8.x4.shared.b16 {%0,%1,%2,%3}, [%4];"
        : "=r"(r0), "=r"(r1), "=r"(r2), "=r"(r3) : "r"(addr));
}

__device__ __forceinline__ void cp16(uint32_t dst, const void* src) {
    asm volatile("cp.async.cg.shared.global [%0], [%1], 16;"
                 :: "r"(dst), "l"(src));
}
#define CP_COMMIT() asm volatile("cp.async.commit_group;" ::: "memory")
#define CP_WAIT0()  asm volatile("cp.async.wait_group 0;" ::: "memory")
#define CP_WAIT1()  asm volatile("cp.async.wait_group 1;" ::: "memory")

// ---------------------------------------------------------------------------
// All-fp16 mma.sync GEMM: C[M,N] = A[M,K] @ B[N,K]^T
// A, B row-major fp16 (K-major). 128x128 CTA tile, BK=64, 8 warps (2x4),
// warp tile 64x32. 3-stage cp.async pipeline, ONE __syncthreads per
// K-iteration (32 iters at K=2048). ldmatrix.x4 fragment loads.
// OUTH=1 -> C fp16, else fp32. Batched via blockIdx.z.
// M, N multiples of 128; K multiple of 64 (>=128).
// ---------------------------------------------------------------------------
#define BM 128
#define BN 128
#define AWS 36      // words per row: 32 data (64 halves) + 4 pad
#define STG (BM * AWS * 4)              // 18432 B per operand stage
#define GEMM_SMEM (6 * STG)             // 3 stages * (A+B) = 110592 B

template <int OUTH>
__global__ __launch_bounds__(256) void gemm_h(
    const __half* __restrict__ A, const __half* __restrict__ B,
    void* __restrict__ Cv, int K, int lda, int ldb, int ldc,
    long long bsA, long long bsB, long long bsC, int bshift)
{
    extern __shared__ uint32_t sm[];

    const int z = blockIdx.z;
    A += (long long)z * bsA;
    B += (long long)(z >> bshift) * bsB;

    const int tid  = threadIdx.x;
    const int wid  = tid >> 5;
    const int lane = tid & 31;
    const int m0 = blockIdx.y * BM;
    const int n0 = blockIdx.x * BN;

    const int wm = (wid >> 2) * 64;
    const int wn = (wid & 3) * 32;
    const int g  = lane >> 2;
    const int t  = lane & 3;

    const uint32_t smb  = smem_u32(sm);
    const uint32_t bsmb = smb + 3 * STG;

    // ldmatrix lane address components (R11-validated pattern, AWS=36:
    // 8-row phase banks (4r+c) mod 32 all distinct)
    const int l7  = lane & 7;
    const int sel = lane >> 3;
    const uint32_t a_lane = ((l7 + ((sel & 1) << 3)) * AWS + ((sel >> 1) << 2)) * 4;
    const uint32_t b_lane = ((l7 + ((sel >> 1) << 3)) * AWS + ((sel & 1) << 2)) * 4;

    float acc[4][4][4];
#pragma unroll
    for (int mt = 0; mt < 4; mt++)
#pragma unroll
        for (int nt = 0; nt < 4; nt++)
#pragma unroll
            for (int r = 0; r < 4; r++) acc[mt][nt][r] = 0.0f;

    // cp.async mapping: 2 threads per 128B row; 4 x 16B chunks per thread
    // per operand per stage.
    const int rc = tid >> 1;            // row 0..127
    const int hc = tid & 1;             // row half (64B)
    uint32_t dof[4];
#pragma unroll
    for (int i = 0; i < 4; i++)
        dof[i] = (uint32_t)((rc * AWS + hc * 16 + i * 4) << 2);
    const __half* arow = A + (size_t)(m0 + rc) * lda + (hc << 5);
    const __half* brow = B + (size_t)(n0 + rc) * ldb + (hc << 5);

    const int nk = K >> 6;

    // prologue: stages 0, 1
#pragma unroll
    for (int s = 0; s < 2; s++) {
        const int k0 = s << 6;
        const uint32_t as_u = smb + s * STG;
        const uint32_t bs_u = bsmb + s * STG;
#pragma unroll
        for (int i = 0; i < 4; i++) {
            cp16(as_u + dof[i], arow + k0 + (i << 3));
            cp16(bs_u + dof[i], brow + k0 + (i << 3));
        }
        CP_COMMIT();
    }

    int stage = 0;
    for (int kt = 0; kt < nk; kt++) {
        if (kt + 1 < nk) { CP_WAIT1(); } else { CP_WAIT0(); }
        __syncthreads();

        // issue loads for stage kt+2 (buffer freed by the sync above)
        if (kt + 2 < nk) {
            const int s2 = (stage + 2 >= 3) ? stage - 1 : stage + 2;
            const int k0 = (kt + 2) << 6;
            const uint32_t as_u = smb + s2 * STG;
            const uint32_t bs_u = bsmb + s2 * STG;
#pragma unroll
            for (int i = 0; i < 4; i++) {
                cp16(as_u + dof[i], arow + k0 + (i << 3));
                cp16(bs_u + dof[i], brow + k0 + (i << 3));
            }
            CP_COMMIT();
        }

        const uint32_t as_b = smb + stage * STG;
        const uint32_t bs_b = bsmb + stage * STG;

#pragma unroll
        for (int kc = 0; kc < 4; kc++) {
            const uint32_t kw = (kc * 8) * 4;
            uint32_t af[4][4], bf[4][2];
#pragma unroll
            for (int mt = 0; mt < 4; mt++)
                ldsm4(af[mt][0], af[mt][1], af[mt][2], af[mt][3],
                      as_b + ((wm + mt * 16) * AWS) * 4 + kw + a_lane);
#pragma unroll
            for (int np = 0; np < 2; np++)
                ldsm4(bf[2 * np][0], bf[2 * np][1],
                      bf[2 * np + 1][0], bf[2 * np + 1][1],
                      bs_b + ((wn + np * 16) * AWS) * 4 + kw + b_lane);
#pragma unroll
            for (int mt = 0; mt < 4; mt++)
#pragma unroll
                for (int nt = 0; nt < 4; nt++)
                    mma_f16(acc[mt][nt][0], acc[mt][nt][1],
                            acc[mt][nt][2], acc[mt][nt][3],
                            af[mt][0], af[mt][1], af[mt][2], af[mt][3],
                            bf[nt][0], bf[nt][1]);
        }
        stage = (stage + 1 >= 3) ? 0 : stage + 1;
    }

    // Epilogue
    if (OUTH) {
        __half* C = (__half*)Cv + (long long)z * bsC;
#pragma unroll
        for (int mt = 0; mt < 4; mt++) {
            const int row = m0 + wm + mt * 16 + g;
#pragma unroll
            for (int nt = 0; nt < 4; nt++) {
                const int col = n0 + wn + nt * 8 + 2 * t;
                *(uint32_t*)(C + (size_t)row * ldc + col) =
                    pk_h2(acc[mt][nt][0], acc[mt][nt][1]);
                *(uint32_t*)(C + (size_t)(row + 8) * ldc + col) =
                    pk_h2(acc[mt][nt][2], acc[mt][nt][3]);
            }
        }
    } else {
        float* C = (float*)Cv + (long long)z * bsC;
#pragma unroll
        for (int mt = 0; mt < 4; mt++) {
            const int row = m0 + wm + mt * 16 + g;
#pragma unroll
            for (int nt = 0; nt < 4; nt++) {
                const int col = n0 + wn + nt * 8 + 2 * t;
                *(float2*)(C + (size_t)row * ldc + col) =
                    make_float2(acc[mt][nt][0], acc[mt][nt][1]);
                *(float2*)(C + (size_t)(row + 8) * ldc + col) =
                    make_float2(acc[mt][nt][2], acc[mt][nt][3]);
            }
        }
    }
}

// ---------------------------------------------------------------------------
// fp32 -> fp16 convert (x), vectorized
// ---------------------------------------------------------------------------
__global__ void cvt16(const float* __restrict__ in, __half* __restrict__ out)
{
    const int i = (blockIdx.x * 256 + threadIdx.x) << 2;
    float4 v = *(const float4*)(in + i);
    uint2 o = make_uint2(pk_h2(v.x, v.y), pk_h2(v.z, v.w));
    *(uint2*)(out + i) = o;
}

// ---------------------------------------------------------------------------
// Tiled transpose fp32 -> fp16 with input stride:
// out is [C, R]; out[x][y] = half(in[y*ldin + x])
// ---------------------------------------------------------------------------
__global__ void transpose_h(const float* __restrict__ in,
                            __half* __restrict__ out, int R, int C, int ldin)
{
    __shared__ float t[32][33];
    const int x = blockIdx.x * 32 + threadIdx.x;
    const int y0 = blockIdx.y * 32 + threadIdx.y;
#pragma unroll
    for (int j = 0; j < 32; j += 8)
        t[threadIdx.y + j][threadIdx.x] = in[(size_t)(y0 + j) * ldin + x];
    __syncthreads();
    const int x2 = blockIdx.y * 32 + threadIdx.x;
    const int y2 = blockIdx.x * 32 + threadIdx.y;
#pragma unroll
    for (int j = 0; j < 32; j += 8)
        out[(size_t)(y2 + j) * R + x2] = __float2half(t[threadIdx.x][threadIdx.y + j]);
}

// ---------------------------------------------------------------------------
// Row softmax: read fp32 S, write fp16 P (scale folded). 1 warp / row.
// ---------------------------------------------------------------------------
__global__ __launch_bounds__(256) void softmax_kernel(
    const float* __restrict__ S, __half* __restrict__ P)
{
    const int row = blockIdx.x * 8 + (threadIdx.x >> 5);
    const int lane = threadIdx.x & 31;
    const float* p = S + (size_t)row * 2048 + lane * 4;
    __half* q = P + (size_t)row * 2048 + lane * 4;

    float4 v[16];
#pragma unroll
    for (int w = 0; w < 16; w++) v[w] = *(const float4*)(p + w * 128);

    float m = -1e30f;
#pragma unroll
    for (int w = 0; w < 16; w++)
        m = fmaxf(m, fmaxf(fmaxf(v[w].x, v[w].y), fmaxf(v[w].z, v[w].w)));
#pragma unroll
    for (int o = 16; o > 0; o >>= 1)
        m = fmaxf(m, __shfl_xor_sync(0xffffffffu, m, o));

    const float ms = m * ATT_SCALE;
    float sum = 0.0f;
#pragma unroll
    for (int w = 0; w < 16; w++) {
        v[w].x = __expf(fmaf(v[w].x, ATT_SCALE, -ms));
        v[w].y = __expf(fmaf(v[w].y, ATT_SCALE, -ms));
        v[w].z = __expf(fmaf(v[w].z, ATT_SCALE, -ms));
        v[w].w = __expf(fmaf(v[w].w, ATT_SCALE, -ms));
        sum += (v[w].x + v[w].y) + (v[w].z + v[w].w);
    }
#pragma unroll
    for (int o = 16; o > 0; o >>= 1)
        sum += __shfl_xor_sync(0xffffffffu, sum, o);

    const float inv = 1.0f / sum;
#pragma unroll
    for (int w = 0; w < 16; w++) {
        uint2 o2 = make_uint2(pk_h2(v[w].x * inv, v[w].y * inv),
                              pk_h2(v[w].z * inv, v[w].w * inv));
        *(uint2*)(q + w * 128) = o2;
    }
}

// ---------------------------------------------------------------------------
// Q rmsnorm (over 256) + rope, fp16 out. grid (TSEQ,16), 256 threads.
// ---------------------------------------------------------------------------
__global__ void qnorm_rope_kernel(
    const float* __restrict__ q, int ld, const float* __restrict__ w,
    const float* __restrict__ sinp, const float* __restrict__ cosp,
    __half* __restrict__ out)
{
    const int t = blockIdx.x, h = blockIdx.y;
    const int tid = threadIdx.x;
    __shared__ float buf[256];
    __shared__ float red[8];

    float v = q[(size_t)t * ld + h * 256 + tid];
    float ss = v * v;
#pragma unroll
    for (int o = 16; o > 0; o >>= 1) ss += __shfl_down_sync(0xffffffffu, ss, o);
    if ((tid & 31) == 0) red[tid >> 5] = ss;
    __syncthreads();
    if (tid < 8) {
        float s = red[tid];
#pragma unroll
        for (int o = 4; o > 0; o >>= 1) s += __shfl_down_sync(0xffu, s, o);
        if (tid == 0) red[0] = s;
    }
    __syncthreads();
    float inv = rsqrtf(red[0] * (1.0f / 256.0f) + 1e-6f);
    buf[tid] = v * inv * w[tid];
    __syncthreads();

    int sub = tid >> 7, d = tid & 127;
    const float* base = buf + (sub << 7);
    int j = (d < 64) ? d : d - 64;
    float c = cosp[t * 64 + j], s = sinp[t * 64 + j];
    float x1 = base[2 * j], x2 = base[2 * j + 1];
    float o = (d < 64) ? (x1 * c - x2 * s) : (x1 * s + x2 * c);
    out[t * QDIM + (h * 2 + sub) * HD + d] = __float2half(o);
}

// ---------------------------------------------------------------------------
// K rmsnorm (over 128) + rope, fp16 out. grid (TSEQ,8), 128 threads.
// ---------------------------------------------------------------------------
__global__ void knorm_rope_kernel(
    const float* __restrict__ k, int ld, const float* __restrict__ w,
    const float* __restrict__ sinp, const float* __restrict__ cosp,
    __half* __restrict__ out)
{
    const int t = blockIdx.x, h = blockIdx.y;
    const int tid = threadIdx.x;
    __shared__ float buf[128];
    __shared__ float red[4];

    float v = k[(size_t)t * ld + h * HD + tid];
    float ss = v * v;
#pragma unroll
    for (int o = 16; o > 0; o >>= 1) ss += __shfl_down_sync(0xffffffffu, ss, o);
    if ((tid & 31) == 0) red[tid >> 5] = ss;
    __syncthreads();
    if (tid < 4) {
        float s = red[tid];
#pragma unroll
        for (int o = 2; o > 0; o >>= 1) s += __shfl_down_sync(0xfu, s, o);
        if (tid == 0) red[0] = s;
    }
    __syncthreads();
    float inv = rsqrtf(red[0] * (1.0f / 128.0f) + 1e-6f);
    buf[tid] = v * inv * w[tid];
    __syncthreads();

    int d = tid;
    int j = (d < 64) ? d : d - 64;
    float c = cosp[t * 64 + j], s = sinp[t * 64 + j];
    float x1 = buf[2 * j], x2 = buf[2 * j + 1];
    float o = (d < 64) ? (x1 * c - x2 * s) : (x1 * s + x2 * c);
    out[t * KVDIM + h * HD + d] = __float2half(o);
}

// ---------------------------------------------------------------------------
// Launch
// ---------------------------------------------------------------------------
extern "C" void kernel_launch(void* const* d_in, const int* in_sizes, int n_in,
                              void* d_out, int out_size)
{
    const float* x    = (const float*)d_in[0];
    const float* Wq   = (const float*)d_in[1];
    const float* Wk   = (const float*)d_in[2];
    const float* Wv   = (const float*)d_in[3];
    const float* Wo   = (const float*)d_in[4];
    const float* qw   = (const float*)d_in[5];
    const float* kw   = (const float*)d_in[6];
    const float* sinp = (const float*)d_in[7];
    const float* cosp = (const float*)d_in[8];
    float* out = (float*)d_out;

    float *pqkv, *ps;
    __half *px16, *pwqkv, *pqr, *pkr, *patt, *pwot, *pvt, *pp;
    cudaGetSymbolAddress((void**)&px16,  g_x16);
    cudaGetSymbolAddress((void**)&pwqkv, g_wqkv);
    cudaGetSymbolAddress((void**)&pqkv,  g_qkv);
    cudaGetSymbolAddress((void**)&pqr,   g_qr);
    cudaGetSymbolAddress((void**)&pkr,   g_kr);
    cudaGetSymbolAddress((void**)&patt,  g_att);
    cudaGetSymbolAddress((void**)&pwot,  g_wot);
    cudaGetSymbolAddress((void**)&pvt,   g_vt);
    cudaGetSymbolAddress((void**)&ps,    g_s);
    cudaGetSymbolAddress((void**)&pp,    g_p);

    cudaFuncSetAttribute(gemm_h<0>, cudaFuncAttributeMaxDynamicSharedMemorySize,
                         GEMM_SMEM);
    cudaFuncSetAttribute(gemm_h<1>, cudaFuncAttributeMaxDynamicSharedMemorySize,
                         GEMM_SMEM);

    dim3 tb(32, 8);
    // x -> fp16
    cvt16<<<(TSEQ * HID) / 1024, 256>>>(x, px16);

    // Weight transposes into merged [6144, 2048] (Wq | Wk | Wv) + Wo
    transpose_h<<<dim3(QDIM / 32, HID / 32), tb>>>(Wq, pwqkv, HID, QDIM, QDIM);
    transpose_h<<<dim3(KVDIM / 32, HID / 32), tb>>>(
        Wk, pwqkv + (size_t)QDIM * HID, HID, KVDIM, KVDIM);
    transpose_h<<<dim3(KVDIM / 32, HID / 32), tb>>>(
        Wv, pwqkv + (size_t)(QDIM + KVDIM) * HID, HID, KVDIM, KVDIM);
    transpose_h<<<dim3(HID / 32, QDIM / 32), tb>>>(Wo, pwot, QDIM, HID, HID);

    // Merged QKV projection: [2048,2048] @ [6144,2048]^T -> [2048,6144] fp32
    gemm_h<0><<<dim3(QKVDIM / BN, TSEQ / BM, 1), 256, GEMM_SMEM>>>(
        px16, pwqkv, pqkv, HID, HID, HID, QKVDIM, 0, 0, 0, 0);

    // Norm + rope (fp16 outputs), reading strided slices of qkv
    qnorm_rope_kernel<<<dim3(TSEQ, NH16), 256>>>(
        pqkv, QKVDIM, qw, sinp, cosp, pqr);
    knorm_rope_kernel<<<dim3(TSEQ, NKV), 128>>>(
        pqkv + QDIM, QKVDIM, kw, sinp, cosp, pkr);

    // V^T (fp16) from the v slice of qkv
    transpose_h<<<dim3(KVDIM / 32, TSEQ / 32), tb>>>(
        pqkv + QDIM + KVDIM, pvt, TSEQ, KVDIM, QKVDIM);

    // S = Q K^T per head (raw logits, fp32), batched over 32 heads
    gemm_h<0><<<dim3(TSEQ / BN, TSEQ / BM, HQ), 256, GEMM_SMEM>>>(
        pqr, pkr, ps, HD, QDIM, KVDIM, TSEQ,
        (long long)HD, (long long)HD, (long long)TSEQ * TSEQ, 2);

    // softmax rows -> fp16 P
    softmax_kernel<<<(HQ * TSEQ) / 8, 256>>>(ps, pp);

    // O = P V per head (fp16 P x fp16 V^T -> fp16 att)
    gemm_h<1><<<dim3(HD / BN, TSEQ / BM, HQ), 256, GEMM_SMEM>>>(
        pp, pvt, patt, TSEQ, TSEQ, TSEQ, QDIM,
        (long long)TSEQ * TSEQ, (long long)HD * TSEQ, (long long)HD, 2);

    // Output projection (fp16 att x fp16 Wo^T -> fp32 out)
    gemm_h<0><<<dim3(HID / BN, TSEQ / BM, 1), 256, GEMM_SMEM>>>(
        patt, pwot, out, QDIM, QDIM, QDIM, HID, 0, 0, 0, 0);
}

// round 17
// speedup vs baseline: 1.3065x; 1.3065x over previous
#include <cuda_runtime.h>
#include <cuda_fp16.h>
#include <cstdint>
#include <math.h>

// ---------------------------------------------------------------------------
// Problem constants
// ---------------------------------------------------------------------------
#define TSEQ   2048
#define HID    2048
#define QDIM   4096   // 32 rope-heads * 128
#define KVDIM  1024   // 8 kv heads * 128
#define QKVDIM 6144   // QDIM + 2*KVDIM (merged projection width)
#define HD     128
#define NH16   16
#define NKV    8
#define HQ     32

#define ATT_SCALE 0.08838834764831845f   // 1/sqrt(128)

// ---------------------------------------------------------------------------
// Static device scratch (no allocations allowed)
// ---------------------------------------------------------------------------
__device__ __half   g_x16 [TSEQ * HID];
__device__ __half   g_wqkv[QKVDIM * HID];     // merged [Wq;Wk;Wv]^T, K-major
__device__ float    g_qkv [TSEQ * QKVDIM];    // merged q|k|v fp32
__device__ __half   g_qr  [TSEQ * QDIM];
__device__ __half   g_kr  [TSEQ * KVDIM];
__device__ __half   g_att [TSEQ * QDIM];
__device__ __half   g_wot [HID * QDIM];
__device__ __half   g_vt  [KVDIM * TSEQ];

// ---------------------------------------------------------------------------
// Helpers
// ---------------------------------------------------------------------------
__device__ __forceinline__ uint32_t pk_h2(float a, float b) {
    __half2 h = __floats2half2_rn(a, b);
    return *reinterpret_cast<uint32_t*>(&h);
}

__device__ __forceinline__ uint32_t smem_u32(const void* p) {
    uint32_t a;
    asm("{ .reg .u64 t; cvta.to.shared.u64 t, %1; cvt.u32.u64 %0, t; }"
        : "=r"(a) : "l"(p));
    return a;
}

__device__ __forceinline__ void mma_f16(
    float& d0, float& d1, float& d2, float& d3,
    uint32_t a0, uint32_t a1, uint32_t a2, uint32_t a3,
    uint32_t b0, uint32_t b1)
{
    asm volatile(
        "mma.sync.aligned.m16n8k16.row.col.f32.f16.f16.f32 "
        "{%0,%1,%2,%3}, {%4,%5,%6,%7}, {%8,%9}, {%0,%1,%2,%3};"
        : "+f"(d0), "+f"(d1), "+f"(d2), "+f"(d3)
        : "r"(a0), "r"(a1), "r"(a2), "r"(a3), "r"(b0), "r"(b1));
}

__device__ __forceinline__ void ldsm4(
    uint32_t& r0, uint32_t& r1, uint32_t& r2, uint32_t& r3, uint32_t addr)
{
    asm volatile(
        "ldmatrix.sync.aligned.m8n8.x4.shared.b16 {%0,%1,%2,%3}, [%4];"
        : "=r"(r0), "=r"(r1), "=r"(r2), "=r"(r3) : "r"(addr));
}

__device__ __forceinline__ void cp16(uint32_t dst, const void* src) {
    asm volatile("cp.async.cg.shared.global [%0], [%1], 16;"
                 :: "r"(dst), "l"(src));
}
#define CP_COMMIT() asm volatile("cp.async.commit_group;" ::: "memory")
#define CP_WAIT0()  asm volatile("cp.async.wait_group 0;" ::: "memory")
#define CP_WAIT1()  asm volatile("cp.async.wait_group 1;" ::: "memory")

// ---------------------------------------------------------------------------
// All-fp16 mma.sync GEMM (R13 config, 797us-validated):
// C[M,N] = A[M,K] @ B[N,K]^T. 128x128 CTA tile, BK=32, 8 warps,
// 3-stage cp.async, one __syncthreads per K-iter, ldmatrix.x4.
// OUTH=1 -> C fp16, else fp32. Batched via blockIdx.z.
// ---------------------------------------------------------------------------
#define BM 128
#define BN 128
#define AWS 20      // half2-word row stride: 16 data + 4 pad
#define STG (BM * AWS * 4)              // bytes per operand stage
#define GEMM_SMEM (6 * STG)             // 3 stages * (A+B) = 61440 B

template <int OUTH>
__global__ __launch_bounds__(256) void gemm_h(
    const __half* __restrict__ A, const __half* __restrict__ B,
    void* __restrict__ Cv, int K, int lda, int ldb, int ldc,
    long long bsA, long long bsB, long long bsC, int bshift)
{
    extern __shared__ uint32_t sm[];

    const int z = blockIdx.z;
    A += (long long)z * bsA;
    B += (long long)(z >> bshift) * bsB;

    const int tid  = threadIdx.x;
    const int wid  = tid >> 5;
    const int lane = tid & 31;
    const int m0 = blockIdx.y * BM;
    const int n0 = blockIdx.x * BN;

    const int wm = (wid >> 2) * 64;
    const int wn = (wid & 3) * 32;
    const int g  = lane >> 2;
    const int t  = lane & 3;

    const uint32_t smb  = smem_u32(sm);
    const uint32_t bsmb = smb + 3 * STG;

    const int l7  = lane & 7;
    const int sel = lane >> 3;
    const uint32_t a_lane = ((l7 + ((sel & 1) << 3)) * AWS + ((sel >> 1) << 2)) * 4;
    const uint32_t b_lane = ((l7 + ((sel >> 1) << 3)) * AWS + ((sel & 1) << 2)) * 4;

    float acc[4][4][4];
#pragma unroll
    for (int mt = 0; mt < 4; mt++)
#pragma unroll
        for (int nt = 0; nt < 4; nt++)
#pragma unroll
            for (int r = 0; r < 4; r++) acc[mt][nt][r] = 0.0f;

    const int r0c = tid >> 2;
    const int off = (tid & 3);
    const uint32_t dlo = (uint32_t)((r0c * AWS + (off << 2)) << 2);
    const uint32_t dhi = (uint32_t)(((r0c + 64) * AWS + (off << 2)) << 2);
    const __half* arow0 = A + (size_t)(m0 + r0c) * lda + (off << 3);
    const __half* arow1 = arow0 + (size_t)64 * lda;
    const __half* brow0 = B + (size_t)(n0 + r0c) * ldb + (off << 3);
    const __half* brow1 = brow0 + (size_t)64 * ldb;

    const int nk = K >> 5;

#pragma unroll
    for (int s = 0; s < 2; s++) {
        const int k0 = s << 5;
        const uint32_t as_u = smb + s * STG;
        const uint32_t bs_u = bsmb + s * STG;
        cp16(as_u + dlo, arow0 + k0);
        cp16(as_u + dhi, arow1 + k0);
        cp16(bs_u + dlo, brow0 + k0);
        cp16(bs_u + dhi, brow1 + k0);
        CP_COMMIT();
    }

    int stage = 0;
    for (int kt = 0; kt < nk; kt++) {
        if (kt + 1 < nk) { CP_WAIT1(); } else { CP_WAIT0(); }
        __syncthreads();

        if (kt + 2 < nk) {
            const int s2 = (stage + 2 >= 3) ? stage - 1 : stage + 2;
            const int k0 = (kt + 2) << 5;
            const uint32_t as_u = smb + s2 * STG;
            const uint32_t bs_u = bsmb + s2 * STG;
            cp16(as_u + dlo, arow0 + k0);
            cp16(as_u + dhi, arow1 + k0);
            cp16(bs_u + dlo, brow0 + k0);
            cp16(bs_u + dhi, brow1 + k0);
            CP_COMMIT();
        }

        const uint32_t as_b = smb + stage * STG;
        const uint32_t bs_b = bsmb + stage * STG;

#pragma unroll
        for (int kc = 0; kc < 2; kc++) {
            const uint32_t kw = (kc * 8) * 4;
            uint32_t af[4][4], bf[4][2];
#pragma unroll
            for (int mt = 0; mt < 4; mt++)
                ldsm4(af[mt][0], af[mt][1], af[mt][2], af[mt][3],
                      as_b + ((wm + mt * 16) * AWS) * 4 + kw + a_lane);
#pragma unroll
            for (int np = 0; np < 2; np++)
                ldsm4(bf[2 * np][0], bf[2 * np][1],
                      bf[2 * np + 1][0], bf[2 * np + 1][1],
                      bs_b + ((wn + np * 16) * AWS) * 4 + kw + b_lane);
#pragma unroll
            for (int mt = 0; mt < 4; mt++)
#pragma unroll
                for (int nt = 0; nt < 4; nt++)
                    mma_f16(acc[mt][nt][0], acc[mt][nt][1],
                            acc[mt][nt][2], acc[mt][nt][3],
                            af[mt][0], af[mt][1], af[mt][2], af[mt][3],
                            bf[nt][0], bf[nt][1]);
        }
        stage = (stage + 1 >= 3) ? 0 : stage + 1;
    }

    if (OUTH) {
        __half* C = (__half*)Cv + (long long)z * bsC;
#pragma unroll
        for (int mt = 0; mt < 4; mt++) {
            const int row = m0 + wm + mt * 16 + g;
#pragma unroll
            for (int nt = 0; nt < 4; nt++) {
                const int col = n0 + wn + nt * 8 + 2 * t;
                *(uint32_t*)(C + (size_t)row * ldc + col) =
                    pk_h2(acc[mt][nt][0], acc[mt][nt][1]);
                *(uint32_t*)(C + (size_t)(row + 8) * ldc + col) =
                    pk_h2(acc[mt][nt][2], acc[mt][nt][3]);
            }
        }
    } else {
        float* C = (float*)Cv + (long long)z * bsC;
#pragma unroll
        for (int mt = 0; mt < 4; mt++) {
            const int row = m0 + wm + mt * 16 + g;
#pragma unroll
            for (int nt = 0; nt < 4; nt++) {
                const int col = n0 + wn + nt * 8 + 2 * t;
                *(float2*)(C + (size_t)row * ldc + col) =
                    make_float2(acc[mt][nt][0], acc[mt][nt][1]);
                *(float2*)(C + (size_t)(row + 8) * ldc + col) =
                    make_float2(acc[mt][nt][2], acc[mt][nt][3]);
            }
        }
    }
}

// ---------------------------------------------------------------------------
// Fused fp16 flash attention.
// CTA = 64 queries x 1 head, 4 warps x 16 rows. 64-key tiles, 2-stage
// cp.async K/V double buffer. Q fragments register-resident. P stays in
// registers (S C-frag layout == PV A-frag layout). Online softmax.
// ---------------------------------------------------------------------------
#define FQT 64      // q rows per CTA
#define FKT 64      // keys per tile
#define KWS 68      // Ks/Qs row stride (words): 64 data + 4 pad
#define VWS 36      // Vt row stride (words): 32 data + 4 pad
#define STG_K (FKT * KWS * 4)            // 17408 B
#define STG_V (HD * VWS * 4)             // 18432 B
#define FA_SMEM (2 * STG_K + 2 * STG_V)  // 71680 B

__global__ __launch_bounds__(128, 3) void flash_h(
    const __half* __restrict__ Q, const __half* __restrict__ K,
    const __half* __restrict__ V, __half* __restrict__ O)
{
    extern __shared__ uint32_t sm[];
    const uint32_t smb   = smem_u32(sm);
    const uint32_t vbase = smb + 2 * STG_K;

    const int tid  = threadIdx.x;
    const int wid  = tid >> 5;
    const int lane = tid & 31;
    const int g = lane >> 2, t = lane & 3;
    const int l7 = lane & 7, sel = lane >> 3;
    const int q0   = blockIdx.x * FQT;
    const int h    = blockIdx.y;
    const int kvh  = h >> 2;
    const int wrow = wid << 4;

    // ldmatrix lane offsets (R11-validated pattern; strides 68/36 both
    // ≡ 4 mod 8 -> same conflict-free property as AWS=20)
    const uint32_t aQ = ((l7 + ((sel & 1) << 3)) * KWS + ((sel >> 1) << 2)) * 4;
    const uint32_t bK = ((l7 + ((sel >> 1) << 3)) * KWS + ((sel & 1) << 2)) * 4;
    const uint32_t bV = ((l7 + ((sel >> 1) << 3)) * VWS + ((sel & 1) << 2)) * 4;

    // cp.async mappings
    const int rc2 = tid >> 1;           // 0..63 (row for Q/K tiles)
    const int hc  = tid & 1;            // 64-half half of row
    const uint32_t kd0 = (uint32_t)((rc2 * KWS + (hc << 5)) << 2);
    const uint32_t vd0 = (uint32_t)((tid * VWS) << 2);
    const __half* krow = K + (size_t)rc2 * KVDIM + kvh * HD + (hc << 6);
    const __half* vrow = V + (size_t)(kvh * HD + tid) * TSEQ;

    // ---- Q tile -> stage-0 K buffer -> registers ----
    {
        const __half* qsrc = Q + (size_t)(q0 + rc2) * QDIM + h * HD + (hc << 6);
#pragma unroll
        for (int i = 0; i < 8; i++)
            cp16(smb + kd0 + (i << 4), qsrc + (i << 3));
    }
    CP_COMMIT(); CP_WAIT0();
    __syncthreads();

    uint32_t qf[8][4];
#pragma unroll
    for (int kc = 0; kc < 8; kc++)
        ldsm4(qf[kc][0], qf[kc][1], qf[kc][2], qf[kc][3],
              smb + (uint32_t)((wrow * KWS) << 2) + (uint32_t)(kc << 5) + aQ);
    __syncthreads();   // all warps done reading Qs before T0 overwrites it

    float o[16][4];
#pragma unroll
    for (int nt = 0; nt < 16; nt++)
#pragma unroll
        for (int r = 0; r < 4; r++) o[nt][r] = 0.0f;
    float m0 = -1e30f, m1 = -1e30f, l0 = 0.0f, l1 = 0.0f;

    // prologue: tile 0 -> buffer 0
#pragma unroll
    for (int i = 0; i < 8; i++) {
        cp16(smb + kd0 + (i << 4), krow + (i << 3));
        cp16(vbase + vd0 + (i << 4), vrow + (i << 3));
    }
    CP_COMMIT();

    const int NKT = TSEQ / FKT;   // 32
    for (int kt = 0; kt < NKT; kt++) {
        const int b = kt & 1;
        __syncthreads();   // all warps done reading buffer b^1 (tile kt-1)
        if (kt + 1 < NKT) {
            const int nb = b ^ 1;
            const int k0 = (kt + 1) << 6;
#pragma unroll
            for (int i = 0; i < 8; i++) {
                cp16(smb + nb * STG_K + kd0 + (i << 4),
                     krow + (size_t)k0 * KVDIM + (i << 3));
                cp16(vbase + nb * STG_V + vd0 + (i << 4),
                     vrow + k0 + (i << 3));
            }
            CP_COMMIT();
            CP_WAIT1();
        } else {
            CP_WAIT0();
        }
        __syncthreads();   // tile kt visible to all warps

        const uint32_t ks_b = smb + b * STG_K;
        const uint32_t vt_b = vbase + b * STG_V;

        // --- S = Q @ K^T  (16 x 64 per warp) ---
        float s[8][4];
#pragma unroll
        for (int nf = 0; nf < 8; nf++)
#pragma unroll
            for (int r = 0; r < 4; r++) s[nf][r] = 0.0f;

#pragma unroll
        for (int kc = 0; kc < 8; kc++) {
            uint32_t bf[8][2];
#pragma unroll
            for (int np = 0; np < 4; np++)
                ldsm4(bf[2 * np][0], bf[2 * np][1],
                      bf[2 * np + 1][0], bf[2 * np + 1][1],
                      ks_b + (uint32_t)(((np * 16) * KWS) << 2)
                           + (uint32_t)(kc << 5) + bK);
#pragma unroll
            for (int nf = 0; nf < 8; nf++)
                mma_f16(s[nf][0], s[nf][1], s[nf][2], s[nf][3],
                        qf[kc][0], qf[kc][1], qf[kc][2], qf[kc][3],
                        bf[nf][0], bf[nf][1]);
        }

        // --- online softmax (rows wrow+g, wrow+g+8; quad-local) ---
#pragma unroll
        for (int nf = 0; nf < 8; nf++)
#pragma unroll
            for (int r = 0; r < 4; r++) s[nf][r] *= ATT_SCALE;

        float mx0 = -1e30f, mx1 = -1e30f;
#pragma unroll
        for (int nf = 0; nf < 8; nf++) {
            mx0 = fmaxf(mx0, fmaxf(s[nf][0], s[nf][1]));
            mx1 = fmaxf(mx1, fmaxf(s[nf][2], s[nf][3]));
        }
        mx0 = fmaxf(mx0, __shfl_xor_sync(0xffffffffu, mx0, 1));
        mx0 = fmaxf(mx0, __shfl_xor_sync(0xffffffffu, mx0, 2));
        mx1 = fmaxf(mx1, __shfl_xor_sync(0xffffffffu, mx1, 1));
        mx1 = fmaxf(mx1, __shfl_xor_sync(0xffffffffu, mx1, 2));

        const float mn0 = fmaxf(m0, mx0);
        const float mn1 = fmaxf(m1, mx1);
        const float a0 = __expf(m0 - mn0);
        const float a1 = __expf(m1 - mn1);
        m0 = mn0; m1 = mn1;

        float sum0 = 0.0f, sum1 = 0.0f;
#pragma unroll
        for (int nf = 0; nf < 8; nf++) {
            s[nf][0] = __expf(s[nf][0] - mn0);
            s[nf][1] = __expf(s[nf][1] - mn0);
            s[nf][2] = __expf(s[nf][2] - mn1);
            s[nf][3] = __expf(s[nf][3] - mn1);
            sum0 += s[nf][0] + s[nf][1];
            sum1 += s[nf][2] + s[nf][3];
        }
        sum0 += __shfl_xor_sync(0xffffffffu, sum0, 1);
        sum0 += __shfl_xor_sync(0xffffffffu, sum0, 2);
        sum1 += __shfl_xor_sync(0xffffffffu, sum1, 1);
        sum1 += __shfl_xor_sync(0xffffffffu, sum1, 2);
        l0 = l0 * a0 + sum0;
        l1 = l1 * a1 + sum1;

        // P fragments: S C-frag layout == PV A-frag layout (FA-2 identity)
        uint32_t pf[4][4];
#pragma unroll
        for (int j = 0; j < 4; j++) {
            pf[j][0] = pk_h2(s[2 * j][0],     s[2 * j][1]);
            pf[j][1] = pk_h2(s[2 * j][2],     s[2 * j][3]);
            pf[j][2] = pk_h2(s[2 * j + 1][0], s[2 * j + 1][1]);
            pf[j][3] = pk_h2(s[2 * j + 1][2], s[2 * j + 1][3]);
        }

        // rescale O accumulators
#pragma unroll
        for (int nt = 0; nt < 16; nt++) {
            o[nt][0] *= a0; o[nt][1] *= a0;
            o[nt][2] *= a1; o[nt][3] *= a1;
        }

        // --- O += P @ V ---
#pragma unroll
        for (int j = 0; j < 4; j++) {
            uint32_t bv[16][2];
#pragma unroll
            for (int np = 0; np < 8; np++)
                ldsm4(bv[2 * np][0], bv[2 * np][1],
                      bv[2 * np + 1][0], bv[2 * np + 1][1],
                      vt_b + (uint32_t)(((np * 16) * VWS) << 2)
                           + (uint32_t)(j << 5) + bV);
#pragma unroll
            for (int nt = 0; nt < 16; nt++)
                mma_f16(o[nt][0], o[nt][1], o[nt][2], o[nt][3],
                        pf[j][0], pf[j][1], pf[j][2], pf[j][3],
                        bv[nt][0], bv[nt][1]);
        }
    }

    // --- normalize + write fp16 ---
    const float i0 = 1.0f / l0;
    const float i1 = 1.0f / l1;
    const int row0 = q0 + wrow + g;
#pragma unroll
    for (int nt = 0; nt < 16; nt++) {
        const int col = h * HD + nt * 8 + 2 * t;
        *(uint32_t*)(O + (size_t)row0 * QDIM + col) =
            pk_h2(o[nt][0] * i0, o[nt][1] * i0);
        *(uint32_t*)(O + (size_t)(row0 + 8) * QDIM + col) =
            pk_h2(o[nt][2] * i1, o[nt][3] * i1);
    }
}

// ---------------------------------------------------------------------------
// fp32 -> fp16 convert (x), vectorized
// ---------------------------------------------------------------------------
__global__ void cvt16(const float* __restrict__ in, __half* __restrict__ out)
{
    const int i = (blockIdx.x * 256 + threadIdx.x) << 2;
    float4 v = *(const float4*)(in + i);
    uint2 o = make_uint2(pk_h2(v.x, v.y), pk_h2(v.z, v.w));
    *(uint2*)(out + i) = o;
}

// ---------------------------------------------------------------------------
// Tiled transpose fp32 -> fp16 with input stride: out is [C, R]
// ---------------------------------------------------------------------------
__global__ void transpose_h(const float* __restrict__ in,
                            __half* __restrict__ out, int R, int C, int ldin)
{
    __shared__ float t[32][33];
    const int x = blockIdx.x * 32 + threadIdx.x;
    const int y0 = blockIdx.y * 32 + threadIdx.y;
#pragma unroll
    for (int j = 0; j < 32; j += 8)
        t[threadIdx.y + j][threadIdx.x] = in[(size_t)(y0 + j) * ldin + x];
    __syncthreads();
    const int x2 = blockIdx.y * 32 + threadIdx.x;
    const int y2 = blockIdx.x * 32 + threadIdx.y;
#pragma unroll
    for (int j = 0; j < 32; j += 8)
        out[(size_t)(y2 + j) * R + x2] = __float2half(t[threadIdx.x][threadIdx.y + j]);
}

// ---------------------------------------------------------------------------
// Q rmsnorm (over 256) + rope, fp16 out. grid (TSEQ,16), 256 threads.
// ---------------------------------------------------------------------------
__global__ void qnorm_rope_kernel(
    const float* __restrict__ q, int ld, const float* __restrict__ w,
    const float* __restrict__ sinp, const float* __restrict__ cosp,
    __half* __restrict__ out)
{
    const int t = blockIdx.x, h = blockIdx.y;
    const int tid = threadIdx.x;
    __shared__ float buf[256];
    __shared__ float red[8];

    float v = q[(size_t)t * ld + h * 256 + tid];
    float ss = v * v;
#pragma unroll
    for (int o = 16; o > 0; o >>= 1) ss += __shfl_down_sync(0xffffffffu, ss, o);
    if ((tid & 31) == 0) red[tid >> 5] = ss;
    __syncthreads();
    if (tid < 8) {
        float s = red[tid];
#pragma unroll
        for (int o = 4; o > 0; o >>= 1) s += __shfl_down_sync(0xffu, s, o);
        if (tid == 0) red[0] = s;
    }
    __syncthreads();
    float inv = rsqrtf(red[0] * (1.0f / 256.0f) + 1e-6f);
    buf[tid] = v * inv * w[tid];
    __syncthreads();

    int sub = tid >> 7, d = tid & 127;
    const float* base = buf + (sub << 7);
    int j = (d < 64) ? d : d - 64;
    float c = cosp[t * 64 + j], s = sinp[t * 64 + j];
    float x1 = base[2 * j], x2 = base[2 * j + 1];
    float o = (d < 64) ? (x1 * c - x2 * s) : (x1 * s + x2 * c);
    out[t * QDIM + (h * 2 + sub) * HD + d] = __float2half(o);
}

// ---------------------------------------------------------------------------
// K rmsnorm (over 128) + rope, fp16 out. grid (TSEQ,8), 128 threads.
// ---------------------------------------------------------------------------
__global__ void knorm_rope_kernel(
    const float* __restrict__ k, int ld, const float* __restrict__ w,
    const float* __restrict__ sinp, const float* __restrict__ cosp,
    __half* __restrict__ out)
{
    const int t = blockIdx.x, h = blockIdx.y;
    const int tid = threadIdx.x;
    __shared__ float buf[128];
    __shared__ float red[4];

    float v = k[(size_t)t * ld + h * HD + tid];
    float ss = v * v;
#pragma unroll
    for (int o = 16; o > 0; o >>= 1) ss += __shfl_down_sync(0xffffffffu, ss, o);
    if ((tid & 31) == 0) red[tid >> 5] = ss;
    __syncthreads();
    if (tid < 4) {
        float s = red[tid];
#pragma unroll
        for (int o = 2; o > 0; o >>= 1) s += __shfl_down_sync(0xfu, s, o);
        if (tid == 0) red[0] = s;
    }
    __syncthreads();
    float inv = rsqrtf(red[0] * (1.0f / 128.0f) + 1e-6f);
    buf[tid] = v * inv * w[tid];
    __syncthreads();

    int d = tid;
    int j = (d < 64) ? d : d - 64;
    float c = cosp[t * 64 + j], s = sinp[t * 64 + j];
    float x1 = buf[2 * j], x2 = buf[2 * j + 1];
    float o = (d < 64) ? (x1 * c - x2 * s) : (x1 * s + x2 * c);
    out[t * KVDIM + h * HD + d] = __float2half(o);
}

// ---------------------------------------------------------------------------
// Launch
// ---------------------------------------------------------------------------
extern "C" void kernel_launch(void* const* d_in, const int* in_sizes, int n_in,
                              void* d_out, int out_size)
{
    const float* x    = (const float*)d_in[0];
    const float* Wq   = (const float*)d_in[1];
    const float* Wk   = (const float*)d_in[2];
    const float* Wv   = (const float*)d_in[3];
    const float* Wo   = (const float*)d_in[4];
    const float* qw   = (const float*)d_in[5];
    const float* kw   = (const float*)d_in[6];
    const float* sinp = (const float*)d_in[7];
    const float* cosp = (const float*)d_in[8];
    float* out = (float*)d_out;

    float* pqkv;
    __half *px16, *pwqkv, *pqr, *pkr, *patt, *pwot, *pvt;
    cudaGetSymbolAddress((void**)&px16,  g_x16);
    cudaGetSymbolAddress((void**)&pwqkv, g_wqkv);
    cudaGetSymbolAddress((void**)&pqkv,  g_qkv);
    cudaGetSymbolAddress((void**)&pqr,   g_qr);
    cudaGetSymbolAddress((void**)&pkr,   g_kr);
    cudaGetSymbolAddress((void**)&patt,  g_att);
    cudaGetSymbolAddress((void**)&pwot,  g_wot);
    cudaGetSymbolAddress((void**)&pvt,   g_vt);

    cudaFuncSetAttribute(gemm_h<0>, cudaFuncAttributeMaxDynamicSharedMemorySize,
                         GEMM_SMEM);
    cudaFuncSetAttribute(flash_h, cudaFuncAttributeMaxDynamicSharedMemorySize,
                         FA_SMEM);

    dim3 tb(32, 8);
    // x -> fp16
    cvt16<<<(TSEQ * HID) / 1024, 256>>>(x, px16);

    // Weight transposes into merged [6144, 2048] (Wq | Wk | Wv) + Wo
    transpose_h<<<dim3(QDIM / 32, HID / 32), tb>>>(Wq, pwqkv, HID, QDIM, QDIM);
    transpose_h<<<dim3(KVDIM / 32, HID / 32), tb>>>(
        Wk, pwqkv + (size_t)QDIM * HID, HID, KVDIM, KVDIM);
    transpose_h<<<dim3(KVDIM / 32, HID / 32), tb>>>(
        Wv, pwqkv + (size_t)(QDIM + KVDIM) * HID, HID, KVDIM, KVDIM);
    transpose_h<<<dim3(HID / 32, QDIM / 32), tb>>>(Wo, pwot, QDIM, HID, HID);

    // Merged QKV projection: [2048,2048] @ [6144,2048]^T -> [2048,6144] fp32
    gemm_h<0><<<dim3(QKVDIM / BN, TSEQ / BM, 1), 256, GEMM_SMEM>>>(
        px16, pwqkv, pqkv, HID, HID, HID, QKVDIM, 0, 0, 0, 0);

    // Norm + rope (fp16 outputs), reading strided slices of qkv
    qnorm_rope_kernel<<<dim3(TSEQ, NH16), 256>>>(
        pqkv, QKVDIM, qw, sinp, cosp, pqr);
    knorm_rope_kernel<<<dim3(TSEQ, NKV), 128>>>(
        pqkv + QDIM, QKVDIM, kw, sinp, cosp, pkr);

    // V^T (fp16) from the v slice of qkv
    transpose_h<<<dim3(KVDIM / 32, TSEQ / 32), tb>>>(
        pqkv + QDIM + KVDIM, pvt, TSEQ, KVDIM, QKVDIM);

    // Fused flash attention: softmax(QK^T * scale) @ V -> fp16 att
    flash_h<<<dim3(TSEQ / FQT, HQ), 128, FA_SMEM>>>(pqr, pkr, pvt, patt);

    // Output projection (fp16 att x fp16 Wo^T -> fp32 out)
    gemm_h<0><<<dim3(HID / BN, TSEQ / BM, 1), 256, GEMM_SMEM>>>(
        patt, pwot, out, QDIM, QDIM, QDIM, HID, 0, 0, 0, 0);
}